// round 1
// baseline (speedup 1.0000x reference)
#include <cuda_runtime.h>
#include <cstdint>

// Problem constants
#define BB 8
#define LL 1024
#define DD 768
#define HH 12
#define DHH 64
#define MM (BB*LL)   // 8192

// Scratch (device globals — no allocation allowed)
__device__ float g_q[BB*HH*LL*DHH];
__device__ float g_k[BB*HH*LL*DHH];
__device__ float g_v[BB*HH*LL*DHH];
__device__ float g_ctx[BB*LL*DD];

// ---------------------------------------------------------------------------
// GEMM: out = X @ W^T + bias.   X: [MM, DD], W: [N=DD rows, K=DD cols] row-major.
// Block tile 128(m) x 64(n), BK=16. 256 threads, 8x4 register micro-tile.
// SCATTER=true: write to [B,H,L,Dh] layout (for Q/K/V projections).
// ---------------------------------------------------------------------------
template<bool SCATTER>
__global__ __launch_bounds__(256)
void gemm_xwt(const float* __restrict__ X, const float* __restrict__ W,
              const float* __restrict__ bias, float* __restrict__ out)
{
    __shared__ float As[16 * 132];   // [k][m], stride 132
    __shared__ float Bs[16 * 68];    // [k][n], stride 68

    const int tid = threadIdx.x;
    const int tx = tid & 15, ty = tid >> 4;
    const int m0 = blockIdx.y * 128;
    const int n0 = blockIdx.x * 64;

    float acc[8][4] = {};

    for (int k0 = 0; k0 < DD; k0 += 16) {
        // Load A tile: 128 rows x 16 k  (transposed into As[k][m])
        #pragma unroll
        for (int t = 0; t < 2; t++) {
            int idx = tid + t * 256;           // 0..511
            int row = idx >> 2;                // 0..127
            int kv  = idx & 3;                 // float4 index along k
            float4 a = *reinterpret_cast<const float4*>(
                X + (size_t)(m0 + row) * DD + k0 + kv * 4);
            As[(kv*4 + 0)*132 + row] = a.x;
            As[(kv*4 + 1)*132 + row] = a.y;
            As[(kv*4 + 2)*132 + row] = a.z;
            As[(kv*4 + 3)*132 + row] = a.w;
        }
        // Load B tile: 64 rows(n) x 16 k (transposed into Bs[k][n])
        {
            int row = tid >> 2;                // 0..63
            int kv  = tid & 3;
            float4 b = *reinterpret_cast<const float4*>(
                W + (size_t)(n0 + row) * DD + k0 + kv * 4);
            Bs[(kv*4 + 0)*68 + row] = b.x;
            Bs[(kv*4 + 1)*68 + row] = b.y;
            Bs[(kv*4 + 2)*68 + row] = b.z;
            Bs[(kv*4 + 3)*68 + row] = b.w;
        }
        __syncthreads();

        #pragma unroll
        for (int k = 0; k < 16; k++) {
            float4 a0 = *reinterpret_cast<const float4*>(As + k*132 + ty*8);
            float4 a1 = *reinterpret_cast<const float4*>(As + k*132 + ty*8 + 4);
            float4 bv = *reinterpret_cast<const float4*>(Bs + k*68 + tx*4);
            float av[8] = {a0.x, a0.y, a0.z, a0.w, a1.x, a1.y, a1.z, a1.w};
            float bw[4] = {bv.x, bv.y, bv.z, bv.w};
            #pragma unroll
            for (int i = 0; i < 8; i++)
                #pragma unroll
                for (int j = 0; j < 4; j++)
                    acc[i][j] = fmaf(av[i], bw[j], acc[i][j]);
        }
        __syncthreads();
    }

    #pragma unroll
    for (int i = 0; i < 8; i++) {
        int m = m0 + ty * 8 + i;
        #pragma unroll
        for (int j = 0; j < 4; j++) {
            int n = n0 + tx * 4 + j;
            float v = acc[i][j] + bias[n];
            if (SCATTER) {
                int b = m >> 10;          // m / L
                int l = m & 1023;
                int h = n >> 6;           // n / Dh
                int d = n & 63;
                out[(((size_t)(b * HH + h) << 10) + l) * DHH + d] = v;
            } else {
                out[(size_t)m * DD + n] = v;
            }
        }
    }
}

// ---------------------------------------------------------------------------
// Fused flash attention. One block per (q-tile of 64 rows, head, batch).
// 256 threads (16x16). Thread owns rows r_i = ty+16i (i<4), cols c_j = tx+16j.
// Online softmax over 16 K-tiles of 64. Handles mask + fully-masked rows.
// ---------------------------------------------------------------------------
__global__ __launch_bounds__(256)
void attn_kernel(const unsigned char* __restrict__ mask, float* __restrict__ ctx)
{
    extern __shared__ float sm[];
    float* q_s  = sm;                     // 64 x 64, stride 64
    float* kp_s = sm + 64 * 64;           // 64 x 65 (K tile, then reused for P)
    float* v_s  = kp_s + 64 * 65;         // 64 x 64, stride 64

    const int tid = threadIdx.x;
    const int tx = tid & 15, ty = tid >> 4;
    const int qt = blockIdx.x, h = blockIdx.y, b = blockIdx.z;

    const size_t head_base = ((size_t)(b * HH + h)) * LL * DHH;
    const float* qg = g_q + head_base + (size_t)qt * 64 * DHH;
    const float* kg = g_k + head_base;
    const float* vg = g_v + head_base;

    // Load Q tile, pre-scaled by 1/sqrt(Dh) = 0.125
    #pragma unroll
    for (int t = 0; t < 4; t++) {
        int idx = tid + t * 256;
        int row = idx >> 4, cv = idx & 15;
        float4 qv = *reinterpret_cast<const float4*>(qg + row * 64 + cv * 4);
        qv.x *= 0.125f; qv.y *= 0.125f; qv.z *= 0.125f; qv.w *= 0.125f;
        *reinterpret_cast<float4*>(q_s + row * 64 + cv * 4) = qv;
    }

    float m_i[4], l_i[4], o[4][4];
    #pragma unroll
    for (int i = 0; i < 4; i++) {
        m_i[i] = -INFINITY; l_i[i] = 0.f;
        #pragma unroll
        for (int j = 0; j < 4; j++) o[i][j] = 0.f;
    }
    __syncthreads();

    for (int kt = 0; kt < LL / 64; kt++) {
        // Load K (stride 65) and V (stride 64) tiles
        const float* kgt = kg + (size_t)kt * 64 * DHH;
        const float* vgt = vg + (size_t)kt * 64 * DHH;
        #pragma unroll
        for (int t = 0; t < 4; t++) {
            int idx = tid + t * 256;
            int row = idx >> 4, cv = idx & 15;
            float4 kv = *reinterpret_cast<const float4*>(kgt + row * 64 + cv * 4);
            float* kd = kp_s + row * 65 + cv * 4;
            kd[0] = kv.x; kd[1] = kv.y; kd[2] = kv.z; kd[3] = kv.w;
            float4 vv = *reinterpret_cast<const float4*>(vgt + row * 64 + cv * 4);
            *reinterpret_cast<float4*>(v_s + row * 64 + cv * 4) = vv;
        }
        __syncthreads();

        // Scores s[i][j] = q[r_i] . k[c_j]   (already scaled via q)
        float s[4][4] = {};
        const float* qr0 = q_s + (ty +  0) * 64;
        const float* qr1 = q_s + (ty + 16) * 64;
        const float* qr2 = q_s + (ty + 32) * 64;
        const float* qr3 = q_s + (ty + 48) * 64;
        const float* kc0 = kp_s + (tx +  0) * 65;
        const float* kc1 = kp_s + (tx + 16) * 65;
        const float* kc2 = kp_s + (tx + 32) * 65;
        const float* kc3 = kp_s + (tx + 48) * 65;
        #pragma unroll 16
        for (int d = 0; d < 64; d++) {
            float qv[4] = {qr0[d], qr1[d], qr2[d], qr3[d]};
            float kv[4] = {kc0[d], kc1[d], kc2[d], kc3[d]};
            #pragma unroll
            for (int i = 0; i < 4; i++)
                #pragma unroll
                for (int j = 0; j < 4; j++)
                    s[i][j] = fmaf(qv[i], kv[j], s[i][j]);
        }

        // Mask
        const unsigned char* mbase =
            mask + ((size_t)b * LL + (size_t)qt * 64) * LL + (size_t)kt * 64;
        bool msk[4][4];
        #pragma unroll
        for (int i = 0; i < 4; i++) {
            const unsigned char* mr = mbase + (size_t)(ty + 16 * i) * LL;
            #pragma unroll
            for (int j = 0; j < 4; j++) {
                msk[i][j] = (mr[tx + 16 * j] != 0);
                if (msk[i][j]) s[i][j] = -INFINITY;
            }
        }

        // Online softmax update
        float p[4][4];
        #pragma unroll
        for (int i = 0; i < 4; i++) {
            float mloc = fmaxf(fmaxf(s[i][0], s[i][1]), fmaxf(s[i][2], s[i][3]));
            #pragma unroll
            for (int off = 8; off >= 1; off >>= 1)
                mloc = fmaxf(mloc, __shfl_xor_sync(0xffffffffu, mloc, off));
            float m_new = fmaxf(m_i[i], mloc);
            float alpha = (m_i[i] == -INFINITY) ? 0.f : __expf(m_i[i] - m_new);
            float rsum = 0.f;
            #pragma unroll
            for (int j = 0; j < 4; j++) {
                p[i][j] = msk[i][j] ? 0.f : __expf(s[i][j] - m_new);
                rsum += p[i][j];
            }
            #pragma unroll
            for (int off = 8; off >= 1; off >>= 1)
                rsum += __shfl_xor_sync(0xffffffffu, rsum, off);
            l_i[i] = l_i[i] * alpha + rsum;
            m_i[i] = m_new;
            #pragma unroll
            for (int j = 0; j < 4; j++) o[i][j] *= alpha;
        }
        __syncthreads();   // all score reads of kp_s done

        // Store P into kp_s (reuse)
        #pragma unroll
        for (int i = 0; i < 4; i++)
            #pragma unroll
            for (int j = 0; j < 4; j++)
                kp_s[(ty + 16 * i) * 65 + (tx + 16 * j)] = p[i][j];
        __syncthreads();

        // O += P @ V
        const float* pr0 = kp_s + (ty +  0) * 65;
        const float* pr1 = kp_s + (ty + 16) * 65;
        const float* pr2 = kp_s + (ty + 32) * 65;
        const float* pr3 = kp_s + (ty + 48) * 65;
        const float* vc0 = v_s + (tx +  0);
        const float* vc1 = v_s + (tx + 16);
        const float* vc2 = v_s + (tx + 32);
        const float* vc3 = v_s + (tx + 48);
        #pragma unroll 16
        for (int kk = 0; kk < 64; kk++) {
            float pv[4] = {pr0[kk], pr1[kk], pr2[kk], pr3[kk]};
            float vv[4] = {vc0[kk * 64], vc1[kk * 64], vc2[kk * 64], vc3[kk * 64]};
            #pragma unroll
            for (int i = 0; i < 4; i++)
                #pragma unroll
                for (int j = 0; j < 4; j++)
                    o[i][j] = fmaf(pv[i], vv[j], o[i][j]);
        }
        __syncthreads();   // before next tile overwrites kp_s / v_s
    }

    // Write context in [B, L, D] layout (head h occupies cols h*64..h*64+63)
    #pragma unroll
    for (int i = 0; i < 4; i++) {
        float inv = (l_i[i] > 0.f) ? (1.f / l_i[i]) : 0.f;   // fully-masked -> 0
        size_t row_g = (size_t)b * LL + (size_t)qt * 64 + (ty + 16 * i);
        #pragma unroll
        for (int j = 0; j < 4; j++) {
            int col = h * 64 + (tx + 16 * j);
            ctx[row_g * DD + col] = o[i][j] * inv;
        }
    }
}

// ---------------------------------------------------------------------------
extern "C" void kernel_launch(void* const* d_in, const int* in_sizes, int n_in,
                              void* d_out, int out_size)
{
    const float* Query = (const float*)d_in[0];
    const float* Key   = (const float*)d_in[1];
    const float* Value = (const float*)d_in[2];
    const unsigned char* maskp = (const unsigned char*)d_in[3];
    const float* WQ_w = (const float*)d_in[4];
    const float* WQ_b = (const float*)d_in[5];
    const float* WK_w = (const float*)d_in[6];
    const float* WK_b = (const float*)d_in[7];
    const float* WV_w = (const float*)d_in[8];
    const float* WV_b = (const float*)d_in[9];
    const float* WO_w = (const float*)d_in[10];
    const float* WO_b = (const float*)d_in[11];
    float* out = (float*)d_out;

    void *qp, *kp, *vp, *cp;
    cudaGetSymbolAddress(&qp, g_q);
    cudaGetSymbolAddress(&kp, g_k);
    cudaGetSymbolAddress(&vp, g_v);
    cudaGetSymbolAddress(&cp, g_ctx);

    static const int smem_attn = (64 * 64 + 64 * 65 + 64 * 64) * 4;  // 49,408 B
    cudaFuncSetAttribute(attn_kernel, cudaFuncAttributeMaxDynamicSharedMemorySize,
                         smem_attn);

    dim3 ggrid(DD / 64, MM / 128);   // (12, 64)
    gemm_xwt<true><<<ggrid, 256>>>(Query, WQ_w, WQ_b, (float*)qp);
    gemm_xwt<true><<<ggrid, 256>>>(Key,   WK_w, WK_b, (float*)kp);
    gemm_xwt<true><<<ggrid, 256>>>(Value, WV_w, WV_b, (float*)vp);

    dim3 agrid(LL / 64, HH, BB);     // (16, 12, 8)
    attn_kernel<<<agrid, 256, smem_attn>>>(maskp, (float*)cp);

    gemm_xwt<false><<<ggrid, 256>>>((const float*)cp, WO_w, WO_b, out);
}

// round 4
// speedup vs baseline: 1.4123x; 1.4123x over previous
#include <cuda_runtime.h>
#include <cuda_bf16.h>
#include <cstdint>

// Problem constants
#define BB 8
#define LL 1024
#define DD 768
#define HH 12
#define DHH 64
#define MM (BB*LL)   // 8192

// ---------------------------------------------------------------------------
// Scratch (device globals — no allocation allowed)
// ---------------------------------------------------------------------------
__device__ float g_q[BB*HH*LL*DHH];
__device__ float g_k[BB*HH*LL*DHH];
__device__ float g_v[BB*HH*LL*DHH];
__device__ float g_ctx[BB*LL*DD];

// bf16 hi/lo splits
__device__ __nv_bfloat16 g_xq_h[MM*DD], g_xq_l[MM*DD];
__device__ __nv_bfloat16 g_xk_h[MM*DD], g_xk_l[MM*DD];
__device__ __nv_bfloat16 g_xv_h[MM*DD], g_xv_l[MM*DD];
__device__ __nv_bfloat16 g_xc_h[MM*DD], g_xc_l[MM*DD];
__device__ __nv_bfloat16 g_wq_h[DD*DD], g_wq_l[DD*DD];
__device__ __nv_bfloat16 g_wk_h[DD*DD], g_wk_l[DD*DD];
__device__ __nv_bfloat16 g_wv_h[DD*DD], g_wv_l[DD*DD];
__device__ __nv_bfloat16 g_wo_h[DD*DD], g_wo_l[DD*DD];

// ---------------------------------------------------------------------------
// PTX helpers — baseline (non-'a') features only: cp.async, ldmatrix, mma.sync
// ---------------------------------------------------------------------------
__device__ __forceinline__ uint32_t smem_u32(const void* p) {
    uint32_t a;
    asm("{ .reg .u64 t; cvta.to.shared.u64 t, %1; cvt.u32.u64 %0, t; }"
        : "=r"(a) : "l"(p));
    return a;
}

__device__ __forceinline__ void cp_async16(uint32_t saddr, const void* gptr) {
    asm volatile("cp.async.cg.shared.global [%0], [%1], 16;"
                 :: "r"(saddr), "l"(gptr) : "memory");
}
__device__ __forceinline__ void cp_commit() {
    asm volatile("cp.async.commit_group;" ::: "memory");
}
template<int N>
__device__ __forceinline__ void cp_wait() {
    asm volatile("cp.async.wait_group %0;" :: "n"(N) : "memory");
}

__device__ __forceinline__ void ldmatrix_x4(uint32_t& r0, uint32_t& r1,
                                            uint32_t& r2, uint32_t& r3,
                                            uint32_t addr) {
    asm volatile("ldmatrix.sync.aligned.m8n8.x4.shared.b16 {%0,%1,%2,%3}, [%4];"
                 : "=r"(r0), "=r"(r1), "=r"(r2), "=r"(r3) : "r"(addr));
}

__device__ __forceinline__ void mma_bf16(float* c, const uint32_t* a,
                                         uint32_t b0, uint32_t b1) {
    asm volatile(
        "mma.sync.aligned.m16n8k16.row.col.f32.bf16.bf16.f32 "
        "{%0,%1,%2,%3}, {%4,%5,%6,%7}, {%8,%9}, {%0,%1,%2,%3};"
        : "+f"(c[0]), "+f"(c[1]), "+f"(c[2]), "+f"(c[3])
        : "r"(a[0]), "r"(a[1]), "r"(a[2]), "r"(a[3]), "r"(b0), "r"(b1));
}

// ---------------------------------------------------------------------------
// fp32 -> (hi, lo) bf16 split.  n4 = element count / 4
// ---------------------------------------------------------------------------
__global__ __launch_bounds__(256)
void split_bf16(const float* __restrict__ x, __nv_bfloat16* __restrict__ hi,
                __nv_bfloat16* __restrict__ lo, int n4)
{
    int i = blockIdx.x * blockDim.x + threadIdx.x;
    if (i >= n4) return;
    float4 v = reinterpret_cast<const float4*>(x)[i];
    __nv_bfloat16 h0 = __float2bfloat16(v.x);
    __nv_bfloat16 h1 = __float2bfloat16(v.y);
    __nv_bfloat16 h2 = __float2bfloat16(v.z);
    __nv_bfloat16 h3 = __float2bfloat16(v.w);
    __nv_bfloat16 l0 = __float2bfloat16(v.x - __bfloat162float(h0));
    __nv_bfloat16 l1 = __float2bfloat16(v.y - __bfloat162float(h1));
    __nv_bfloat16 l2 = __float2bfloat16(v.z - __bfloat162float(h2));
    __nv_bfloat16 l3 = __float2bfloat16(v.w - __bfloat162float(h3));
    __nv_bfloat162* hp = reinterpret_cast<__nv_bfloat162*>(hi);
    __nv_bfloat162* lp = reinterpret_cast<__nv_bfloat162*>(lo);
    hp[2*i]   = __nv_bfloat162(h0, h1);
    hp[2*i+1] = __nv_bfloat162(h2, h3);
    lp[2*i]   = __nv_bfloat162(l0, l1);
    lp[2*i+1] = __nv_bfloat162(l2, l3);
}

// ---------------------------------------------------------------------------
// HMMA GEMM: out[8192,768] = A @ W^T + bias via bf16 hi/lo 3-term split.
// Block 128x128, BK=32, 8 warps (warp tile 32x64), cp.async double buffer.
// Smem rows padded to 80B (40 bf16) -> conflict-free ldmatrix & decent stores.
// ---------------------------------------------------------------------------
#define ROW_B   80                       // bytes per smem row (32 bf16 + pad)
#define TILE_B  (128 * ROW_B)            // 10240 B per tile
#define STAGE_B (4 * TILE_B)             // Ah, Al, Bh, Bl = 40960 B
#define NCHUNK  (DD / 32)                // 24

template<bool SCATTER>
__global__ __launch_bounds__(256)
void gemm_mma(const __nv_bfloat16* __restrict__ Ah, const __nv_bfloat16* __restrict__ Al,
              const __nv_bfloat16* __restrict__ Bh, const __nv_bfloat16* __restrict__ Bl,
              const float* __restrict__ bias, float* __restrict__ out)
{
    extern __shared__ __align__(128) char smem[];
    const uint32_t sbase = smem_u32(smem);

    const int tid  = threadIdx.x;
    const int wid  = tid >> 5, lane = tid & 31;
    const int wm   = wid & 3;            // warp m index (rows wm*32)
    const int wn   = wid >> 2;           // warp n index (cols wn*64)
    const int m0   = blockIdx.y * 128;
    const int n0   = blockIdx.x * 128;

    const __nv_bfloat16* srcs[4] = {
        Ah + (size_t)m0 * DD, Al + (size_t)m0 * DD,
        Bh + (size_t)n0 * DD, Bl + (size_t)n0 * DD
    };

    // async-load one K-chunk (32 cols) of all 4 tiles into stage st
    auto load_chunk = [&](int kc, int st) {
        const int k0 = kc * 32;
        #pragma unroll
        for (int t = 0; t < 8; t++) {
            int id   = tid + t * 256;        // 0..2047
            int tile = id >> 9;              // 0..3
            int rem  = id & 511;
            int row  = rem >> 2;             // 0..127
            int seg  = rem & 3;              // 16B segment in row
            const __nv_bfloat16* g = srcs[tile] + (size_t)row * DD + k0 + seg * 8;
            uint32_t s = sbase + st * STAGE_B + tile * TILE_B + row * ROW_B + seg * 16;
            cp_async16(s, g);
        }
        cp_commit();
    };

    float acc[2][8][4];
    #pragma unroll
    for (int i = 0; i < 2; i++)
        #pragma unroll
        for (int j = 0; j < 8; j++)
            #pragma unroll
            for (int k = 0; k < 4; k++) acc[i][j][k] = 0.f;

    load_chunk(0, 0);

    #pragma unroll 1
    for (int c = 0; c < NCHUNK; c++) {
        const int s = c & 1;
        if (c + 1 < NCHUNK) { load_chunk(c + 1, s ^ 1); cp_wait<1>(); }
        else                { cp_wait<0>(); }
        __syncthreads();

        const uint32_t stg = sbase + s * STAGE_B;
        const int lrow = lane & 15;
        const int lhalf = lane >> 4;

        #pragma unroll
        for (int ks = 0; ks < 2; ks++) {
            const int seg = ks * 2 + lhalf;
            uint32_t ah[2][4], al[2][4], bh[4][4], bl[4][4];
            #pragma unroll
            for (int mf = 0; mf < 2; mf++) {
                uint32_t off = (uint32_t)((wm * 32 + mf * 16 + lrow) * ROW_B + seg * 16);
                ldmatrix_x4(ah[mf][0], ah[mf][1], ah[mf][2], ah[mf][3], stg + off);
                ldmatrix_x4(al[mf][0], al[mf][1], al[mf][2], al[mf][3], stg + TILE_B + off);
            }
            #pragma unroll
            for (int ng = 0; ng < 4; ng++) {
                uint32_t off = (uint32_t)((wn * 64 + ng * 16 + lrow) * ROW_B + seg * 16);
                ldmatrix_x4(bh[ng][0], bh[ng][1], bh[ng][2], bh[ng][3], stg + 2*TILE_B + off);
                ldmatrix_x4(bl[ng][0], bl[ng][1], bl[ng][2], bl[ng][3], stg + 3*TILE_B + off);
            }
            #pragma unroll
            for (int mf = 0; mf < 2; mf++) {
                #pragma unroll
                for (int ng = 0; ng < 4; ng++) {
                    // n8 frag low (rows n0-7): regs {r0, r2}; high: {r1, r3}
                    mma_bf16(acc[mf][2*ng  ], ah[mf], bh[ng][0], bh[ng][2]);
                    mma_bf16(acc[mf][2*ng+1], ah[mf], bh[ng][1], bh[ng][3]);
                    mma_bf16(acc[mf][2*ng  ], ah[mf], bl[ng][0], bl[ng][2]);
                    mma_bf16(acc[mf][2*ng+1], ah[mf], bl[ng][1], bl[ng][3]);
                    mma_bf16(acc[mf][2*ng  ], al[mf], bh[ng][0], bh[ng][2]);
                    mma_bf16(acc[mf][2*ng+1], al[mf], bh[ng][1], bh[ng][3]);
                }
            }
        }
        __syncthreads();
    }

    // Epilogue: accumulator (16x8 frag): c0,c1 at (lane/4, (lane%4)*2), c2,c3 at +8 rows
    #pragma unroll
    for (int nf = 0; nf < 8; nf++) {
        const int col = n0 + wn * 64 + nf * 8 + (lane & 3) * 2;
        const float b0 = bias[col], b1 = bias[col + 1];
        #pragma unroll
        for (int mf = 0; mf < 2; mf++) {
            const int r0 = m0 + wm * 32 + mf * 16 + (lane >> 2);
            const float* a = acc[mf][nf];
            #pragma unroll
            for (int half = 0; half < 2; half++) {
                const int m = r0 + half * 8;
                float2 v = make_float2(a[2*half] + b0, a[2*half+1] + b1);
                float* dst;
                if (SCATTER) {
                    int bb = m >> 10, l = m & 1023;
                    int h = col >> 6, d = col & 63;
                    dst = out + (((size_t)(bb * HH + h) << 10) + l) * DHH + d;
                } else {
                    dst = out + (size_t)m * DD + col;
                }
                *reinterpret_cast<float2*>(dst) = v;
            }
        }
    }
}

// ---------------------------------------------------------------------------
// Fused flash attention (round-1, fp32 SIMT — unchanged)
// ---------------------------------------------------------------------------
__global__ __launch_bounds__(256)
void attn_kernel(const unsigned char* __restrict__ mask, float* __restrict__ ctx)
{
    extern __shared__ float sm[];
    float* q_s  = sm;                     // 64 x 64, stride 64
    float* kp_s = sm + 64 * 64;           // 64 x 65 (K tile, then reused for P)
    float* v_s  = kp_s + 64 * 65;         // 64 x 64, stride 64

    const int tid = threadIdx.x;
    const int tx = tid & 15, ty = tid >> 4;
    const int qt = blockIdx.x, h = blockIdx.y, b = blockIdx.z;

    const size_t head_base = ((size_t)(b * HH + h)) * LL * DHH;
    const float* qg = g_q + head_base + (size_t)qt * 64 * DHH;
    const float* kg = g_k + head_base;
    const float* vg = g_v + head_base;

    #pragma unroll
    for (int t = 0; t < 4; t++) {
        int idx = tid + t * 256;
        int row = idx >> 4, cv = idx & 15;
        float4 qv = *reinterpret_cast<const float4*>(qg + row * 64 + cv * 4);
        qv.x *= 0.125f; qv.y *= 0.125f; qv.z *= 0.125f; qv.w *= 0.125f;
        *reinterpret_cast<float4*>(q_s + row * 64 + cv * 4) = qv;
    }

    float m_i[4], l_i[4], o[4][4];
    #pragma unroll
    for (int i = 0; i < 4; i++) {
        m_i[i] = -INFINITY; l_i[i] = 0.f;
        #pragma unroll
        for (int j = 0; j < 4; j++) o[i][j] = 0.f;
    }
    __syncthreads();

    for (int kt = 0; kt < LL / 64; kt++) {
        const float* kgt = kg + (size_t)kt * 64 * DHH;
        const float* vgt = vg + (size_t)kt * 64 * DHH;
        #pragma unroll
        for (int t = 0; t < 4; t++) {
            int idx = tid + t * 256;
            int row = idx >> 4, cv = idx & 15;
            float4 kv = *reinterpret_cast<const float4*>(kgt + row * 64 + cv * 4);
            float* kd = kp_s + row * 65 + cv * 4;
            kd[0] = kv.x; kd[1] = kv.y; kd[2] = kv.z; kd[3] = kv.w;
            float4 vv = *reinterpret_cast<const float4*>(vgt + row * 64 + cv * 4);
            *reinterpret_cast<float4*>(v_s + row * 64 + cv * 4) = vv;
        }
        __syncthreads();

        float s[4][4] = {};
        const float* qr0 = q_s + (ty +  0) * 64;
        const float* qr1 = q_s + (ty + 16) * 64;
        const float* qr2 = q_s + (ty + 32) * 64;
        const float* qr3 = q_s + (ty + 48) * 64;
        const float* kc0 = kp_s + (tx +  0) * 65;
        const float* kc1 = kp_s + (tx + 16) * 65;
        const float* kc2 = kp_s + (tx + 32) * 65;
        const float* kc3 = kp_s + (tx + 48) * 65;
        #pragma unroll 16
        for (int d = 0; d < 64; d++) {
            float qv[4] = {qr0[d], qr1[d], qr2[d], qr3[d]};
            float kv[4] = {kc0[d], kc1[d], kc2[d], kc3[d]};
            #pragma unroll
            for (int i = 0; i < 4; i++)
                #pragma unroll
                for (int j = 0; j < 4; j++)
                    s[i][j] = fmaf(qv[i], kv[j], s[i][j]);
        }

        const unsigned char* mbase =
            mask + ((size_t)b * LL + (size_t)qt * 64) * LL + (size_t)kt * 64;
        bool msk[4][4];
        #pragma unroll
        for (int i = 0; i < 4; i++) {
            const unsigned char* mr = mbase + (size_t)(ty + 16 * i) * LL;
            #pragma unroll
            for (int j = 0; j < 4; j++) {
                msk[i][j] = (mr[tx + 16 * j] != 0);
                if (msk[i][j]) s[i][j] = -INFINITY;
            }
        }

        float p[4][4];
        #pragma unroll
        for (int i = 0; i < 4; i++) {
            float mloc = fmaxf(fmaxf(s[i][0], s[i][1]), fmaxf(s[i][2], s[i][3]));
            #pragma unroll
            for (int off = 8; off >= 1; off >>= 1)
                mloc = fmaxf(mloc, __shfl_xor_sync(0xffffffffu, mloc, off));
            float m_new = fmaxf(m_i[i], mloc);
            float alpha = (m_i[i] == -INFINITY) ? 0.f : __expf(m_i[i] - m_new);
            float rsum = 0.f;
            #pragma unroll
            for (int j = 0; j < 4; j++) {
                p[i][j] = msk[i][j] ? 0.f : __expf(s[i][j] - m_new);
                rsum += p[i][j];
            }
            #pragma unroll
            for (int off = 8; off >= 1; off >>= 1)
                rsum += __shfl_xor_sync(0xffffffffu, rsum, off);
            l_i[i] = l_i[i] * alpha + rsum;
            m_i[i] = m_new;
            #pragma unroll
            for (int j = 0; j < 4; j++) o[i][j] *= alpha;
        }
        __syncthreads();

        #pragma unroll
        for (int i = 0; i < 4; i++)
            #pragma unroll
            for (int j = 0; j < 4; j++)
                kp_s[(ty + 16 * i) * 65 + (tx + 16 * j)] = p[i][j];
        __syncthreads();

        const float* pr0 = kp_s + (ty +  0) * 65;
        const float* pr1 = kp_s + (ty + 16) * 65;
        const float* pr2 = kp_s + (ty + 32) * 65;
        const float* pr3 = kp_s + (ty + 48) * 65;
        const float* vc0 = v_s + (tx +  0);
        const float* vc1 = v_s + (tx + 16);
        const float* vc2 = v_s + (tx + 32);
        const float* vc3 = v_s + (tx + 48);
        #pragma unroll 16
        for (int kk = 0; kk < 64; kk++) {
            float pv[4] = {pr0[kk], pr1[kk], pr2[kk], pr3[kk]};
            float vv[4] = {vc0[kk * 64], vc1[kk * 64], vc2[kk * 64], vc3[kk * 64]};
            #pragma unroll
            for (int i = 0; i < 4; i++)
                #pragma unroll
                for (int j = 0; j < 4; j++)
                    o[i][j] = fmaf(pv[i], vv[j], o[i][j]);
        }
        __syncthreads();
    }

    #pragma unroll
    for (int i = 0; i < 4; i++) {
        float inv = (l_i[i] > 0.f) ? (1.f / l_i[i]) : 0.f;
        size_t row_g = (size_t)b * LL + (size_t)qt * 64 + (ty + 16 * i);
        #pragma unroll
        for (int j = 0; j < 4; j++) {
            int col = h * 64 + (tx + 16 * j);
            ctx[row_g * DD + col] = o[i][j] * inv;
        }
    }
}

// ---------------------------------------------------------------------------
extern "C" void kernel_launch(void* const* d_in, const int* in_sizes, int n_in,
                              void* d_out, int out_size)
{
    const float* Query = (const float*)d_in[0];
    const float* Key   = (const float*)d_in[1];
    const float* Value = (const float*)d_in[2];
    const unsigned char* maskp = (const unsigned char*)d_in[3];
    const float* WQ_b = (const float*)d_in[5];
    const float* WK_b = (const float*)d_in[7];
    const float* WV_b = (const float*)d_in[9];
    const float* WO_b = (const float*)d_in[11];
    const float* Ws[4] = {(const float*)d_in[4], (const float*)d_in[6],
                          (const float*)d_in[8], (const float*)d_in[10]};
    float* out = (float*)d_out;

    void *qp, *kp, *vp, *cp;
    cudaGetSymbolAddress(&qp, g_q);
    cudaGetSymbolAddress(&kp, g_k);
    cudaGetSymbolAddress(&vp, g_v);
    cudaGetSymbolAddress(&cp, g_ctx);

    void *xqh, *xql, *xkh, *xkl, *xvh, *xvl, *xch, *xcl;
    cudaGetSymbolAddress(&xqh, g_xq_h); cudaGetSymbolAddress(&xql, g_xq_l);
    cudaGetSymbolAddress(&xkh, g_xk_h); cudaGetSymbolAddress(&xkl, g_xk_l);
    cudaGetSymbolAddress(&xvh, g_xv_h); cudaGetSymbolAddress(&xvl, g_xv_l);
    cudaGetSymbolAddress(&xch, g_xc_h); cudaGetSymbolAddress(&xcl, g_xc_l);
    void *wh[4], *wl[4];
    cudaGetSymbolAddress(&wh[0], g_wq_h); cudaGetSymbolAddress(&wl[0], g_wq_l);
    cudaGetSymbolAddress(&wh[1], g_wk_h); cudaGetSymbolAddress(&wl[1], g_wk_l);
    cudaGetSymbolAddress(&wh[2], g_wv_h); cudaGetSymbolAddress(&wl[2], g_wv_l);
    cudaGetSymbolAddress(&wh[3], g_wo_h); cudaGetSymbolAddress(&wl[3], g_wo_l);

    static const int smem_attn = (64 * 64 + 64 * 65 + 64 * 64) * 4;  // 49,408 B
    cudaFuncSetAttribute(attn_kernel, cudaFuncAttributeMaxDynamicSharedMemorySize,
                         smem_attn);
    cudaFuncSetAttribute(gemm_mma<true>, cudaFuncAttributeMaxDynamicSharedMemorySize,
                         2 * STAGE_B);
    cudaFuncSetAttribute(gemm_mma<false>, cudaFuncAttributeMaxDynamicSharedMemorySize,
                         2 * STAGE_B);

    const int nx4 = MM * DD / 4;    // input tensors / 4
    const int nw4 = DD * DD / 4;    // weights / 4

    // Split weights + inputs to bf16 hi/lo
    for (int i = 0; i < 4; i++)
        split_bf16<<<(nw4 + 255) / 256, 256>>>(Ws[i], (__nv_bfloat16*)wh[i],
                                               (__nv_bfloat16*)wl[i], nw4);
    split_bf16<<<(nx4 + 255) / 256, 256>>>(Query, (__nv_bfloat16*)xqh,
                                           (__nv_bfloat16*)xql, nx4);
    split_bf16<<<(nx4 + 255) / 256, 256>>>(Key,   (__nv_bfloat16*)xkh,
                                           (__nv_bfloat16*)xkl, nx4);
    split_bf16<<<(nx4 + 255) / 256, 256>>>(Value, (__nv_bfloat16*)xvh,
                                           (__nv_bfloat16*)xvl, nx4);

    // Projections (HMMA), scattered to [B,H,L,Dh]
    dim3 ggrid(DD / 128, MM / 128);   // (6, 64)
    gemm_mma<true><<<ggrid, 256, 2 * STAGE_B>>>(
        (const __nv_bfloat16*)xqh, (const __nv_bfloat16*)xql,
        (const __nv_bfloat16*)wh[0], (const __nv_bfloat16*)wl[0], WQ_b, (float*)qp);
    gemm_mma<true><<<ggrid, 256, 2 * STAGE_B>>>(
        (const __nv_bfloat16*)xkh, (const __nv_bfloat16*)xkl,
        (const __nv_bfloat16*)wh[1], (const __nv_bfloat16*)wl[1], WK_b, (float*)kp);
    gemm_mma<true><<<ggrid, 256, 2 * STAGE_B>>>(
        (const __nv_bfloat16*)xvh, (const __nv_bfloat16*)xvl,
        (const __nv_bfloat16*)wh[2], (const __nv_bfloat16*)wl[2], WV_b, (float*)vp);

    // Attention
    dim3 agrid(LL / 64, HH, BB);     // (16, 12, 8)
    attn_kernel<<<agrid, 256, smem_attn>>>(maskp, (float*)cp);

    // Output projection
    split_bf16<<<(nx4 + 255) / 256, 256>>>((const float*)cp, (__nv_bfloat16*)xch,
                                           (__nv_bfloat16*)xcl, nx4);
    gemm_mma<false><<<ggrid, 256, 2 * STAGE_B>>>(
        (const __nv_bfloat16*)xch, (const __nv_bfloat16*)xcl,
        (const __nv_bfloat16*)wh[3], (const __nv_bfloat16*)wl[3], WO_b, out);
}

// round 5
// speedup vs baseline: 2.5095x; 1.7769x over previous
#include <cuda_runtime.h>
#include <cuda_bf16.h>
#include <cstdint>

// Problem constants
#define BB 8
#define LL 1024
#define DD 768
#define HH 12
#define DHH 64
#define MM (BB*LL)   // 8192

// ---------------------------------------------------------------------------
// Scratch (device globals — no allocation allowed)
// ---------------------------------------------------------------------------
// Q/K/V projections as bf16 hi/lo, [B, H, L, Dh]
__device__ __nv_bfloat16 g_qh[BB*HH*LL*DHH], g_ql[BB*HH*LL*DHH];
__device__ __nv_bfloat16 g_kh[BB*HH*LL*DHH], g_kl[BB*HH*LL*DHH];
__device__ __nv_bfloat16 g_vh[BB*HH*LL*DHH], g_vl[BB*HH*LL*DHH];
// attention context hi/lo, [M, D]
__device__ __nv_bfloat16 g_ch[MM*DD], g_cl[MM*DD];
// input hi/lo splits [M, D]
__device__ __nv_bfloat16 g_xq_h[MM*DD], g_xq_l[MM*DD];
__device__ __nv_bfloat16 g_xk_h[MM*DD], g_xk_l[MM*DD];
__device__ __nv_bfloat16 g_xv_h[MM*DD], g_xv_l[MM*DD];
// weight hi/lo splits [D, D]
__device__ __nv_bfloat16 g_wq_h[DD*DD], g_wq_l[DD*DD];
__device__ __nv_bfloat16 g_wk_h[DD*DD], g_wk_l[DD*DD];
__device__ __nv_bfloat16 g_wv_h[DD*DD], g_wv_l[DD*DD];
__device__ __nv_bfloat16 g_wo_h[DD*DD], g_wo_l[DD*DD];
// bit-packed mask [B, L, L/32] + per-tile flags [B, 8, 8]
__device__ uint32_t g_mbits[BB*LL*(LL/32)];
__device__ unsigned char g_mflags[BB*8*8];

// ---------------------------------------------------------------------------
// PTX helpers — baseline (non-'a') features only
// ---------------------------------------------------------------------------
__device__ __forceinline__ uint32_t smem_u32(const void* p) {
    uint32_t a;
    asm("{ .reg .u64 t; cvta.to.shared.u64 t, %1; cvt.u32.u64 %0, t; }"
        : "=r"(a) : "l"(p));
    return a;
}
__device__ __forceinline__ void cp_async16(uint32_t saddr, const void* gptr) {
    asm volatile("cp.async.cg.shared.global [%0], [%1], 16;"
                 :: "r"(saddr), "l"(gptr) : "memory");
}
__device__ __forceinline__ void cp_commit() {
    asm volatile("cp.async.commit_group;" ::: "memory");
}
template<int N>
__device__ __forceinline__ void cp_wait() {
    asm volatile("cp.async.wait_group %0;" :: "n"(N) : "memory");
}
__device__ __forceinline__ void ldmatrix_x4(uint32_t& r0, uint32_t& r1,
                                            uint32_t& r2, uint32_t& r3,
                                            uint32_t addr) {
    asm volatile("ldmatrix.sync.aligned.m8n8.x4.shared.b16 {%0,%1,%2,%3}, [%4];"
                 : "=r"(r0), "=r"(r1), "=r"(r2), "=r"(r3) : "r"(addr));
}
__device__ __forceinline__ void ldmatrix_x4_t(uint32_t& r0, uint32_t& r1,
                                              uint32_t& r2, uint32_t& r3,
                                              uint32_t addr) {
    asm volatile("ldmatrix.sync.aligned.m8n8.x4.trans.shared.b16 {%0,%1,%2,%3}, [%4];"
                 : "=r"(r0), "=r"(r1), "=r"(r2), "=r"(r3) : "r"(addr));
}
__device__ __forceinline__ void mma_bf16(float* c, const uint32_t* a,
                                         uint32_t b0, uint32_t b1) {
    asm volatile(
        "mma.sync.aligned.m16n8k16.row.col.f32.bf16.bf16.f32 "
        "{%0,%1,%2,%3}, {%4,%5,%6,%7}, {%8,%9}, {%0,%1,%2,%3};"
        : "+f"(c[0]), "+f"(c[1]), "+f"(c[2]), "+f"(c[3])
        : "r"(a[0]), "r"(a[1]), "r"(a[2]), "r"(a[3]), "r"(b0), "r"(b1));
}
__device__ __forceinline__ void split2(float v0, float v1,
                                       uint32_t& hi, uint32_t& lo) {
    __nv_bfloat16 h0 = __float2bfloat16(v0), h1 = __float2bfloat16(v1);
    __nv_bfloat162 hp(h0, h1);
    hi = *reinterpret_cast<uint32_t*>(&hp);
    __nv_bfloat16 l0 = __float2bfloat16(v0 - __bfloat162float(h0));
    __nv_bfloat16 l1 = __float2bfloat16(v1 - __bfloat162float(h1));
    __nv_bfloat162 lp(l0, l1);
    lo = *reinterpret_cast<uint32_t*>(&lp);
}

// ---------------------------------------------------------------------------
// Mask preprocessing: bool bytes -> bit words; per (b, qtile128, ktile128) flags
// ---------------------------------------------------------------------------
__global__ __launch_bounds__(256)
void pack_mask(const unsigned char* __restrict__ mask, uint32_t* __restrict__ bits)
{
    int i = blockIdx.x * blockDim.x + threadIdx.x;   // word index, < B*L*L/32
    const uint4* p = reinterpret_cast<const uint4*>(mask + (size_t)i * 32);
    uint4 u0 = p[0], u1 = p[1];
    uint32_t ws[8] = {u0.x, u0.y, u0.z, u0.w, u1.x, u1.y, u1.z, u1.w};
    uint32_t r = 0;
    #pragma unroll
    for (int w = 0; w < 8; w++)
        #pragma unroll
        for (int k = 0; k < 4; k++)
            if ((ws[w] >> (8 * k)) & 0xFFu) r |= 1u << (w * 4 + k);
    bits[i] = r;
}

__global__ __launch_bounds__(128)
void mask_flags(const uint32_t* __restrict__ bits, unsigned char* __restrict__ flags)
{
    int kt = blockIdx.x, qt = blockIdx.y, b = blockIdx.z;
    int row = qt * 128 + threadIdx.x;
    const uint32_t* p = bits + ((size_t)(b * LL + row)) * (LL / 32) + kt * 4;
    uint32_t v = p[0] | p[1] | p[2] | p[3];
    int any = __syncthreads_or(v != 0);
    if (threadIdx.x == 0) flags[(b * 8 + qt) * 8 + kt] = (unsigned char)any;
}

// ---------------------------------------------------------------------------
// fp32 -> (hi, lo) bf16 split.  n4 = element count / 4
// ---------------------------------------------------------------------------
__global__ __launch_bounds__(256)
void split_bf16(const float* __restrict__ x, __nv_bfloat16* __restrict__ hi,
                __nv_bfloat16* __restrict__ lo, int n4)
{
    int i = blockIdx.x * blockDim.x + threadIdx.x;
    if (i >= n4) return;
    float4 v = reinterpret_cast<const float4*>(x)[i];
    uint32_t h0, l0, h1, l1;
    split2(v.x, v.y, h0, l0);
    split2(v.z, v.w, h1, l1);
    uint32_t* hp = reinterpret_cast<uint32_t*>(hi);
    uint32_t* lp = reinterpret_cast<uint32_t*>(lo);
    hp[2*i] = h0; hp[2*i+1] = h1;
    lp[2*i] = l0; lp[2*i+1] = l1;
}

// ---------------------------------------------------------------------------
// HMMA GEMM: out[8192,768] = A @ W^T + bias via bf16 hi/lo 3-term split.
// EPI 0: fp32 output [M, D].  EPI 1: bf16 hi/lo split, scattered [B,H,L,Dh], *scale.
// ---------------------------------------------------------------------------
#define ROW_B   80
#define TILE_B  (128 * ROW_B)
#define STAGE_B (4 * TILE_B)
#define NCHUNK  (DD / 32)

template<int EPI>
__global__ __launch_bounds__(256)
void gemm_mma(const __nv_bfloat16* __restrict__ Ah, const __nv_bfloat16* __restrict__ Al,
              const __nv_bfloat16* __restrict__ Bh, const __nv_bfloat16* __restrict__ Bl,
              const float* __restrict__ bias, float scale,
              float* __restrict__ outf,
              __nv_bfloat16* __restrict__ oh, __nv_bfloat16* __restrict__ ol)
{
    extern __shared__ __align__(128) char smem[];
    const uint32_t sbase = smem_u32(smem);

    const int tid  = threadIdx.x;
    const int wid  = tid >> 5, lane = tid & 31;
    const int wm   = wid & 3;
    const int wn   = wid >> 2;
    const int m0   = blockIdx.y * 128;
    const int n0   = blockIdx.x * 128;

    const __nv_bfloat16* srcs[4] = {
        Ah + (size_t)m0 * DD, Al + (size_t)m0 * DD,
        Bh + (size_t)n0 * DD, Bl + (size_t)n0 * DD
    };

    auto load_chunk = [&](int kc, int st) {
        const int k0 = kc * 32;
        #pragma unroll
        for (int t = 0; t < 8; t++) {
            int id   = tid + t * 256;
            int tile = id >> 9;
            int rem  = id & 511;
            int row  = rem >> 2;
            int seg  = rem & 3;
            const __nv_bfloat16* g = srcs[tile] + (size_t)row * DD + k0 + seg * 8;
            uint32_t s = sbase + st * STAGE_B + tile * TILE_B + row * ROW_B + seg * 16;
            cp_async16(s, g);
        }
        cp_commit();
    };

    float acc[2][8][4];
    #pragma unroll
    for (int i = 0; i < 2; i++)
        #pragma unroll
        for (int j = 0; j < 8; j++)
            #pragma unroll
            for (int k = 0; k < 4; k++) acc[i][j][k] = 0.f;

    load_chunk(0, 0);

    #pragma unroll 1
    for (int c = 0; c < NCHUNK; c++) {
        const int s = c & 1;
        if (c + 1 < NCHUNK) { load_chunk(c + 1, s ^ 1); cp_wait<1>(); }
        else                { cp_wait<0>(); }
        __syncthreads();

        const uint32_t stg = sbase + s * STAGE_B;
        const int lrow = lane & 15;
        const int lhalf = lane >> 4;

        #pragma unroll
        for (int ks = 0; ks < 2; ks++) {
            const int seg = ks * 2 + lhalf;
            uint32_t ah[2][4], al[2][4], bh[4][4], bl[4][4];
            #pragma unroll
            for (int mf = 0; mf < 2; mf++) {
                uint32_t off = (uint32_t)((wm * 32 + mf * 16 + lrow) * ROW_B + seg * 16);
                ldmatrix_x4(ah[mf][0], ah[mf][1], ah[mf][2], ah[mf][3], stg + off);
                ldmatrix_x4(al[mf][0], al[mf][1], al[mf][2], al[mf][3], stg + TILE_B + off);
            }
            #pragma unroll
            for (int ng = 0; ng < 4; ng++) {
                uint32_t off = (uint32_t)((wn * 64 + ng * 16 + lrow) * ROW_B + seg * 16);
                ldmatrix_x4(bh[ng][0], bh[ng][1], bh[ng][2], bh[ng][3], stg + 2*TILE_B + off);
                ldmatrix_x4(bl[ng][0], bl[ng][1], bl[ng][2], bl[ng][3], stg + 3*TILE_B + off);
            }
            #pragma unroll
            for (int mf = 0; mf < 2; mf++) {
                #pragma unroll
                for (int ng = 0; ng < 4; ng++) {
                    mma_bf16(acc[mf][2*ng  ], ah[mf], bh[ng][0], bh[ng][2]);
                    mma_bf16(acc[mf][2*ng+1], ah[mf], bh[ng][1], bh[ng][3]);
                    mma_bf16(acc[mf][2*ng  ], ah[mf], bl[ng][0], bl[ng][2]);
                    mma_bf16(acc[mf][2*ng+1], ah[mf], bl[ng][1], bl[ng][3]);
                    mma_bf16(acc[mf][2*ng  ], al[mf], bh[ng][0], bh[ng][2]);
                    mma_bf16(acc[mf][2*ng+1], al[mf], bh[ng][1], bh[ng][3]);
                }
            }
        }
        __syncthreads();
    }

    #pragma unroll
    for (int nf = 0; nf < 8; nf++) {
        const int col = n0 + wn * 64 + nf * 8 + (lane & 3) * 2;
        const float b0 = bias[col], b1 = bias[col + 1];
        #pragma unroll
        for (int mf = 0; mf < 2; mf++) {
            const int r0 = m0 + wm * 32 + mf * 16 + (lane >> 2);
            const float* a = acc[mf][nf];
            #pragma unroll
            for (int half = 0; half < 2; half++) {
                const int m = r0 + half * 8;
                float v0 = a[2*half] + b0, v1 = a[2*half+1] + b1;
                if (EPI == 0) {
                    *reinterpret_cast<float2*>(outf + (size_t)m * DD + col)
                        = make_float2(v0, v1);
                } else {
                    v0 *= scale; v1 *= scale;
                    uint32_t hp, lp;
                    split2(v0, v1, hp, lp);
                    int bb = m >> 10, l = m & 1023;
                    int hh = col >> 6, d = col & 63;
                    size_t idx = (((size_t)(bb * HH + hh) << 10) + l) * DHH + d;
                    *reinterpret_cast<uint32_t*>(oh + idx) = hp;
                    *reinterpret_cast<uint32_t*>(ol + idx) = lp;
                }
            }
        }
    }
}

// ---------------------------------------------------------------------------
// HMMA flash attention.
// Block = 128 Q rows x (h, b); 8 warps, warp owns 16 rows x full 128 kv cols.
// 3-term hi/lo split on both QK^T and PV. Online softmax in registers.
// Writes ctx as bf16 hi/lo [M, D].
// ---------------------------------------------------------------------------
#define AROW    72                      // halves per smem row (64 + pad)
#define AROWB   144
#define ATILE_B (128 * AROWB)           // 18432 B
#define KVSTG_B (4 * ATILE_B)           // Kh,Kl,Vh,Vl = 73728 B
#define ASMEM   (2 * ATILE_B + 2 * KVSTG_B)   // 184320 B

__global__ __launch_bounds__(256, 1)
void attn_mma(const __nv_bfloat16* __restrict__ Qh, const __nv_bfloat16* __restrict__ Ql,
              const __nv_bfloat16* __restrict__ Kh, const __nv_bfloat16* __restrict__ Kl,
              const __nv_bfloat16* __restrict__ Vh, const __nv_bfloat16* __restrict__ Vl,
              const uint32_t* __restrict__ mbits,
              const unsigned char* __restrict__ mflags,
              __nv_bfloat16* __restrict__ Ch, __nv_bfloat16* __restrict__ Cl)
{
    extern __shared__ __align__(128) char smem[];
    const uint32_t sb = smem_u32(smem);
    const int tid = threadIdx.x, wid = tid >> 5, lane = tid & 31;
    const int qt = blockIdx.x, h = blockIdx.y, b = blockIdx.z;
    const int q0 = qt * 128;
    const size_t hb = ((size_t)(b * HH + h)) << 16;   // * L * Dh

    const uint32_t SQH = sb, SQL = sb + ATILE_B;
    auto stage = [&](int s) { return sb + 2 * ATILE_B + (uint32_t)s * KVSTG_B; };

    auto load_tile = [&](const __nv_bfloat16* g, uint32_t s) {
        #pragma unroll
        for (int it = 0; it < 4; it++) {
            int id = tid + it * 256;
            int row = id >> 3, seg = id & 7;
            cp_async16(s + row * AROWB + seg * 16, g + (size_t)row * 64 + seg * 8);
        }
    };
    auto load_kv = [&](int t, int s) {
        const size_t off = hb + (size_t)t * 128 * 64;
        uint32_t st = stage(s);
        load_tile(Kh + off, st);
        load_tile(Kl + off, st + ATILE_B);
        load_tile(Vh + off, st + 2 * ATILE_B);
        load_tile(Vl + off, st + 3 * ATILE_B);
        cp_commit();
    };

    load_tile(Qh + hb + (size_t)q0 * 64, SQH);
    load_tile(Ql + hb + (size_t)q0 * 64, SQL);
    cp_commit();
    load_kv(0, 0);
    cp_wait<1>();      // Q ready
    __syncthreads();

    // Q fragments in registers (A-operand, 4 dh-ksteps)
    const int lr = lane & 15, lh = lane >> 4;
    uint32_t qfh[4][4], qfl[4][4];
    #pragma unroll
    for (int ks = 0; ks < 4; ks++) {
        uint32_t off = (uint32_t)((wid * 16 + lr) * AROWB + ks * 32 + lh * 16);
        ldmatrix_x4(qfh[ks][0], qfh[ks][1], qfh[ks][2], qfh[ks][3], SQH + off);
        ldmatrix_x4(qfl[ks][0], qfl[ks][1], qfl[ks][2], qfl[ks][3], SQL + off);
    }

    float mA = -INFINITY, mB = -INFINITY, lA = 0.f, lB = 0.f;
    float o[8][4];
    #pragma unroll
    for (int i = 0; i < 8; i++)
        #pragma unroll
        for (int j = 0; j < 4; j++) o[i][j] = 0.f;

    const unsigned char* flagp = mflags + (b * 8 + qt) * 8;

    #pragma unroll 1
    for (int t = 0; t < 8; t++) {
        if (t < 7) { load_kv(t + 1, (t + 1) & 1); cp_wait<1>(); }
        else       { cp_wait<0>(); }
        __syncthreads();
        const uint32_t st = stage(t & 1);

        // ---- S = Q @ K^T (3 terms) ----
        float s[16][4];
        #pragma unroll
        for (int j = 0; j < 16; j++)
            #pragma unroll
            for (int k = 0; k < 4; k++) s[j][k] = 0.f;

        #pragma unroll
        for (int ks = 0; ks < 4; ks++) {
            #pragma unroll
            for (int ng = 0; ng < 8; ng++) {
                uint32_t off = (uint32_t)((ng * 16 + lr) * AROWB + ks * 32 + lh * 16);
                uint32_t k0, k1, k2, k3, l0, l1, l2, l3;
                ldmatrix_x4(k0, k1, k2, k3, st + off);
                ldmatrix_x4(l0, l1, l2, l3, st + ATILE_B + off);
                mma_bf16(s[2*ng  ], qfh[ks], k0, k2);
                mma_bf16(s[2*ng+1], qfh[ks], k1, k3);
                mma_bf16(s[2*ng  ], qfh[ks], l0, l2);
                mma_bf16(s[2*ng+1], qfh[ks], l1, l3);
                mma_bf16(s[2*ng  ], qfl[ks], k0, k2);
                mma_bf16(s[2*ng+1], qfl[ks], k1, k3);
            }
        }

        // ---- mask (rare path; tile-level flag) ----
        if (flagp[t]) {
            const uint32_t* mr = mbits
                + ((size_t)(b * LL + q0 + wid * 16 + (lane >> 2))) * (LL / 32) + t * 4;
            uint32_t wA[4], wB[4];
            #pragma unroll
            for (int ww = 0; ww < 4; ww++) { wA[ww] = mr[ww]; wB[ww] = mr[8 * (LL/32) + ww]; }
            #pragma unroll
            for (int j = 0; j < 16; j++) {
                int bp = (j & 3) * 8 + (lane & 3) * 2;
                uint32_t a = wA[j >> 2], bw = wB[j >> 2];
                if ((a  >> bp)      & 1u) s[j][0] = -INFINITY;
                if ((a  >> (bp+1))  & 1u) s[j][1] = -INFINITY;
                if ((bw >> bp)      & 1u) s[j][2] = -INFINITY;
                if ((bw >> (bp+1))  & 1u) s[j][3] = -INFINITY;
            }
        }

        // ---- online softmax (rows A: l>>2, B: +8) ----
        float mxA = -INFINITY, mxB = -INFINITY;
        #pragma unroll
        for (int j = 0; j < 16; j++) {
            mxA = fmaxf(mxA, fmaxf(s[j][0], s[j][1]));
            mxB = fmaxf(mxB, fmaxf(s[j][2], s[j][3]));
        }
        mxA = fmaxf(mxA, __shfl_xor_sync(0xffffffffu, mxA, 1));
        mxA = fmaxf(mxA, __shfl_xor_sync(0xffffffffu, mxA, 2));
        mxB = fmaxf(mxB, __shfl_xor_sync(0xffffffffu, mxB, 1));
        mxB = fmaxf(mxB, __shfl_xor_sync(0xffffffffu, mxB, 2));
        float mnA = fmaxf(mA, mxA), mnB = fmaxf(mB, mxB);
        float aA = (mA == -INFINITY) ? 0.f : __expf(mA - mnA);
        float aB = (mB == -INFINITY) ? 0.f : __expf(mB - mnB);
        float subA = (mnA == -INFINITY) ? 0.f : mnA;
        float subB = (mnB == -INFINITY) ? 0.f : mnB;
        float sA = 0.f, sB = 0.f;
        #pragma unroll
        for (int j = 0; j < 16; j++) {
            s[j][0] = __expf(s[j][0] - subA);
            s[j][1] = __expf(s[j][1] - subA);
            s[j][2] = __expf(s[j][2] - subB);
            s[j][3] = __expf(s[j][3] - subB);
            sA += s[j][0] + s[j][1];
            sB += s[j][2] + s[j][3];
        }
        sA += __shfl_xor_sync(0xffffffffu, sA, 1);
        sA += __shfl_xor_sync(0xffffffffu, sA, 2);
        sB += __shfl_xor_sync(0xffffffffu, sB, 1);
        sB += __shfl_xor_sync(0xffffffffu, sB, 2);
        lA = lA * aA + sA; lB = lB * aB + sB;
        mA = mnA; mB = mnB;
        #pragma unroll
        for (int nf = 0; nf < 8; nf++) {
            o[nf][0] *= aA; o[nf][1] *= aA;
            o[nf][2] *= aB; o[nf][3] *= aB;
        }

        // ---- O += P @ V (3 terms); P repacked in-register to bf16 hi/lo ----
        #pragma unroll
        for (int ks = 0; ks < 8; ks++) {
            uint32_t aph[4], apl[4];
            split2(s[2*ks  ][0], s[2*ks  ][1], aph[0], apl[0]);
            split2(s[2*ks  ][2], s[2*ks  ][3], aph[1], apl[1]);
            split2(s[2*ks+1][0], s[2*ks+1][1], aph[2], apl[2]);
            split2(s[2*ks+1][2], s[2*ks+1][3], aph[3], apl[3]);
            #pragma unroll
            for (int ng = 0; ng < 4; ng++) {
                uint32_t voff = (uint32_t)((ks * 16 + lr) * AROWB + ng * 32 + lh * 16);
                uint32_t v0, v1, v2, v3, w0, w1, w2, w3;
                ldmatrix_x4_t(v0, v1, v2, v3, st + 2 * ATILE_B + voff);
                ldmatrix_x4_t(w0, w1, w2, w3, st + 3 * ATILE_B + voff);
                mma_bf16(o[2*ng  ], aph, v0, v1);
                mma_bf16(o[2*ng+1], aph, v2, v3);
                mma_bf16(o[2*ng  ], aph, w0, w1);
                mma_bf16(o[2*ng+1], aph, w2, w3);
                mma_bf16(o[2*ng  ], apl, v0, v1);
                mma_bf16(o[2*ng+1], apl, v2, v3);
            }
        }
        __syncthreads();
    }

    // ---- epilogue: normalize, split to bf16 hi/lo, write ctx [M, D] ----
    float iA = (lA > 0.f) ? (1.f / lA) : 0.f;
    float iB = (lB > 0.f) ? (1.f / lB) : 0.f;
    size_t rowA = (size_t)b * LL + q0 + wid * 16 + (lane >> 2);
    size_t rowB = rowA + 8;
    #pragma unroll
    for (int nf = 0; nf < 8; nf++) {
        int col = h * 64 + nf * 8 + (lane & 3) * 2;
        uint32_t hp, lp;
        split2(o[nf][0] * iA, o[nf][1] * iA, hp, lp);
        *reinterpret_cast<uint32_t*>(Ch + rowA * DD + col) = hp;
        *reinterpret_cast<uint32_t*>(Cl + rowA * DD + col) = lp;
        split2(o[nf][2] * iB, o[nf][3] * iB, hp, lp);
        *reinterpret_cast<uint32_t*>(Ch + rowB * DD + col) = hp;
        *reinterpret_cast<uint32_t*>(Cl + rowB * DD + col) = lp;
    }
}

// ---------------------------------------------------------------------------
extern "C" void kernel_launch(void* const* d_in, const int* in_sizes, int n_in,
                              void* d_out, int out_size)
{
    const float* Query = (const float*)d_in[0];
    const float* Key   = (const float*)d_in[1];
    const float* Value = (const float*)d_in[2];
    const unsigned char* maskp = (const unsigned char*)d_in[3];
    const float* WQ_b = (const float*)d_in[5];
    const float* WK_b = (const float*)d_in[7];
    const float* WV_b = (const float*)d_in[9];
    const float* WO_b = (const float*)d_in[11];
    const float* Ws[4] = {(const float*)d_in[4], (const float*)d_in[6],
                          (const float*)d_in[8], (const float*)d_in[10]};
    float* out = (float*)d_out;

    void *qh, *ql, *kh, *kl, *vh, *vl, *ch, *cl, *mb, *mf;
    cudaGetSymbolAddress(&qh, g_qh); cudaGetSymbolAddress(&ql, g_ql);
    cudaGetSymbolAddress(&kh, g_kh); cudaGetSymbolAddress(&kl, g_kl);
    cudaGetSymbolAddress(&vh, g_vh); cudaGetSymbolAddress(&vl, g_vl);
    cudaGetSymbolAddress(&ch, g_ch); cudaGetSymbolAddress(&cl, g_cl);
    cudaGetSymbolAddress(&mb, g_mbits); cudaGetSymbolAddress(&mf, g_mflags);

    void *xh[3], *xl[3];
    cudaGetSymbolAddress(&xh[0], g_xq_h); cudaGetSymbolAddress(&xl[0], g_xq_l);
    cudaGetSymbolAddress(&xh[1], g_xk_h); cudaGetSymbolAddress(&xl[1], g_xk_l);
    cudaGetSymbolAddress(&xh[2], g_xv_h); cudaGetSymbolAddress(&xl[2], g_xv_l);
    void *wh[4], *wl[4];
    cudaGetSymbolAddress(&wh[0], g_wq_h); cudaGetSymbolAddress(&wl[0], g_wq_l);
    cudaGetSymbolAddress(&wh[1], g_wk_h); cudaGetSymbolAddress(&wl[1], g_wk_l);
    cudaGetSymbolAddress(&wh[2], g_wv_h); cudaGetSymbolAddress(&wl[2], g_wv_l);
    cudaGetSymbolAddress(&wh[3], g_wo_h); cudaGetSymbolAddress(&wl[3], g_wo_l);

    cudaFuncSetAttribute(gemm_mma<0>, cudaFuncAttributeMaxDynamicSharedMemorySize,
                         2 * STAGE_B);
    cudaFuncSetAttribute(gemm_mma<1>, cudaFuncAttributeMaxDynamicSharedMemorySize,
                         2 * STAGE_B);
    cudaFuncSetAttribute(attn_mma, cudaFuncAttributeMaxDynamicSharedMemorySize,
                         ASMEM);

    // Mask preprocessing
    const int nwords = BB * LL * (LL / 32);          // 262144
    pack_mask<<<nwords / 256, 256>>>(maskp, (uint32_t*)mb);
    mask_flags<<<dim3(8, 8, 8), 128>>>((const uint32_t*)mb, (unsigned char*)mf);

    // Splits
    const int nx4 = MM * DD / 4;
    const int nw4 = DD * DD / 4;
    for (int i = 0; i < 4; i++)
        split_bf16<<<(nw4 + 255) / 256, 256>>>(Ws[i], (__nv_bfloat16*)wh[i],
                                               (__nv_bfloat16*)wl[i], nw4);
    split_bf16<<<(nx4 + 255) / 256, 256>>>(Query, (__nv_bfloat16*)xh[0],
                                           (__nv_bfloat16*)xl[0], nx4);
    split_bf16<<<(nx4 + 255) / 256, 256>>>(Key,   (__nv_bfloat16*)xh[1],
                                           (__nv_bfloat16*)xl[1], nx4);
    split_bf16<<<(nx4 + 255) / 256, 256>>>(Value, (__nv_bfloat16*)xh[2],
                                           (__nv_bfloat16*)xl[2], nx4);

    // Projections -> bf16 hi/lo [B,H,L,Dh]; Q pre-scaled by 1/sqrt(Dh)
    dim3 ggrid(DD / 128, MM / 128);
    gemm_mma<1><<<ggrid, 256, 2 * STAGE_B>>>(
        (const __nv_bfloat16*)xh[0], (const __nv_bfloat16*)xl[0],
        (const __nv_bfloat16*)wh[0], (const __nv_bfloat16*)wl[0], WQ_b, 0.125f,
        nullptr, (__nv_bfloat16*)qh, (__nv_bfloat16*)ql);
    gemm_mma<1><<<ggrid, 256, 2 * STAGE_B>>>(
        (const __nv_bfloat16*)xh[1], (const __nv_bfloat16*)xl[1],
        (const __nv_bfloat16*)wh[1], (const __nv_bfloat16*)wl[1], WK_b, 1.0f,
        nullptr, (__nv_bfloat16*)kh, (__nv_bfloat16*)kl);
    gemm_mma<1><<<ggrid, 256, 2 * STAGE_B>>>(
        (const __nv_bfloat16*)xh[2], (const __nv_bfloat16*)xl[2],
        (const __nv_bfloat16*)wh[2], (const __nv_bfloat16*)wl[2], WV_b, 1.0f,
        nullptr, (__nv_bfloat16*)vh, (__nv_bfloat16*)vl);

    // Attention -> ctx hi/lo [M, D]
    dim3 agrid(LL / 128, HH, BB);    // (8, 12, 8)
    attn_mma<<<agrid, 256, ASMEM>>>(
        (const __nv_bfloat16*)qh, (const __nv_bfloat16*)ql,
        (const __nv_bfloat16*)kh, (const __nv_bfloat16*)kl,
        (const __nv_bfloat16*)vh, (const __nv_bfloat16*)vl,
        (const uint32_t*)mb, (const unsigned char*)mf,
        (__nv_bfloat16*)ch, (__nv_bfloat16*)cl);

    // Output projection -> fp32 d_out
    gemm_mma<0><<<ggrid, 256, 2 * STAGE_B>>>(
        (const __nv_bfloat16*)ch, (const __nv_bfloat16*)cl,
        (const __nv_bfloat16*)wh[3], (const __nv_bfloat16*)wl[3], WO_b, 1.0f,
        out, nullptr, nullptr);
}

// round 6
// speedup vs baseline: 2.7154x; 1.0821x over previous
#include <cuda_runtime.h>
#include <cuda_bf16.h>
#include <cstdint>

// Problem constants
#define BB 8
#define LL 1024
#define DD 768
#define HH 12
#define DHH 64
#define MM (BB*LL)   // 8192
#define LOG2E 1.4426950408889634f

// ---------------------------------------------------------------------------
// Scratch (device globals — no allocation allowed)
// ---------------------------------------------------------------------------
__device__ __nv_bfloat16 g_qh[BB*HH*LL*DHH], g_ql[BB*HH*LL*DHH];
__device__ __nv_bfloat16 g_kh[BB*HH*LL*DHH], g_kl[BB*HH*LL*DHH];
__device__ __nv_bfloat16 g_vh[BB*HH*LL*DHH], g_vl[BB*HH*LL*DHH];
__device__ __nv_bfloat16 g_ch[MM*DD], g_cl[MM*DD];
__device__ __nv_bfloat16 g_xq_h[MM*DD], g_xq_l[MM*DD];
__device__ __nv_bfloat16 g_xk_h[MM*DD], g_xk_l[MM*DD];
__device__ __nv_bfloat16 g_xv_h[MM*DD], g_xv_l[MM*DD];
__device__ __nv_bfloat16 g_wq_h[DD*DD], g_wq_l[DD*DD];
__device__ __nv_bfloat16 g_wk_h[DD*DD], g_wk_l[DD*DD];
__device__ __nv_bfloat16 g_wv_h[DD*DD], g_wv_l[DD*DD];
__device__ __nv_bfloat16 g_wo_h[DD*DD], g_wo_l[DD*DD];
__device__ uint32_t g_mbits[BB*LL*(LL/32)];
__device__ unsigned char g_mflags[BB*8*8];

// ---------------------------------------------------------------------------
// PTX helpers — baseline (non-'a') features only
// ---------------------------------------------------------------------------
__device__ __forceinline__ uint32_t smem_u32(const void* p) {
    uint32_t a;
    asm("{ .reg .u64 t; cvta.to.shared.u64 t, %1; cvt.u32.u64 %0, t; }"
        : "=r"(a) : "l"(p));
    return a;
}
__device__ __forceinline__ void cp_async16(uint32_t saddr, const void* gptr) {
    asm volatile("cp.async.cg.shared.global [%0], [%1], 16;"
                 :: "r"(saddr), "l"(gptr) : "memory");
}
__device__ __forceinline__ void cp_commit() {
    asm volatile("cp.async.commit_group;" ::: "memory");
}
template<int N>
__device__ __forceinline__ void cp_wait() {
    asm volatile("cp.async.wait_group %0;" :: "n"(N) : "memory");
}
__device__ __forceinline__ void ldmatrix_x4(uint32_t& r0, uint32_t& r1,
                                            uint32_t& r2, uint32_t& r3,
                                            uint32_t addr) {
    asm volatile("ldmatrix.sync.aligned.m8n8.x4.shared.b16 {%0,%1,%2,%3}, [%4];"
                 : "=r"(r0), "=r"(r1), "=r"(r2), "=r"(r3) : "r"(addr));
}
__device__ __forceinline__ void ldmatrix_x4_t(uint32_t& r0, uint32_t& r1,
                                              uint32_t& r2, uint32_t& r3,
                                              uint32_t addr) {
    asm volatile("ldmatrix.sync.aligned.m8n8.x4.trans.shared.b16 {%0,%1,%2,%3}, [%4];"
                 : "=r"(r0), "=r"(r1), "=r"(r2), "=r"(r3) : "r"(addr));
}
__device__ __forceinline__ void mma_bf16(float* c, const uint32_t* a,
                                         uint32_t b0, uint32_t b1) {
    asm volatile(
        "mma.sync.aligned.m16n8k16.row.col.f32.bf16.bf16.f32 "
        "{%0,%1,%2,%3}, {%4,%5,%6,%7}, {%8,%9}, {%0,%1,%2,%3};"
        : "+f"(c[0]), "+f"(c[1]), "+f"(c[2]), "+f"(c[3])
        : "r"(a[0]), "r"(a[1]), "r"(a[2]), "r"(a[3]), "r"(b0), "r"(b1));
}
__device__ __forceinline__ void split2(float v0, float v1,
                                       uint32_t& hi, uint32_t& lo) {
    __nv_bfloat162 h = __floats2bfloat162_rn(v0, v1);
    hi = *reinterpret_cast<uint32_t*>(&h);
    float2 hf = __bfloat1622float2(h);
    __nv_bfloat162 l = __floats2bfloat162_rn(v0 - hf.x, v1 - hf.y);
    lo = *reinterpret_cast<uint32_t*>(&l);
}

// ---------------------------------------------------------------------------
// Mask preprocessing
// ---------------------------------------------------------------------------
__global__ __launch_bounds__(256)
void pack_mask(const unsigned char* __restrict__ mask)
{
    int i = blockIdx.x * blockDim.x + threadIdx.x;
    const uint4* p = reinterpret_cast<const uint4*>(mask + (size_t)i * 32);
    uint4 u0 = p[0], u1 = p[1];
    uint32_t ws[8] = {u0.x, u0.y, u0.z, u0.w, u1.x, u1.y, u1.z, u1.w};
    uint32_t r = 0;
    #pragma unroll
    for (int w = 0; w < 8; w++)
        #pragma unroll
        for (int k = 0; k < 4; k++)
            if ((ws[w] >> (8 * k)) & 0xFFu) r |= 1u << (w * 4 + k);
    g_mbits[i] = r;
}

__global__ __launch_bounds__(128)
void mask_flags()
{
    int kt = blockIdx.x, qt = blockIdx.y, b = blockIdx.z;
    int row = qt * 128 + threadIdx.x;
    const uint32_t* p = g_mbits + ((size_t)(b * LL + row)) * (LL / 32) + kt * 4;
    uint32_t v = p[0] | p[1] | p[2] | p[3];
    int any = __syncthreads_or(v != 0);
    if (threadIdx.x == 0) g_mflags[(b * 8 + qt) * 8 + kt] = (unsigned char)any;
}

// ---------------------------------------------------------------------------
// Splits: inputs (z=0..2) and weights (z=0..3), to device-global hi/lo
// ---------------------------------------------------------------------------
__global__ __launch_bounds__(256)
void split_x(const float* __restrict__ q, const float* __restrict__ k,
             const float* __restrict__ v)
{
    int z = blockIdx.z;
    const float* src = (z == 0) ? q : (z == 1) ? k : v;
    __nv_bfloat16* hi = (z == 0) ? g_xq_h : (z == 1) ? g_xk_h : g_xv_h;
    __nv_bfloat16* lo = (z == 0) ? g_xq_l : (z == 1) ? g_xk_l : g_xv_l;
    int i = blockIdx.x * blockDim.x + threadIdx.x;
    float4 f = reinterpret_cast<const float4*>(src)[i];
    uint32_t h0, l0, h1, l1;
    split2(f.x, f.y, h0, l0);
    split2(f.z, f.w, h1, l1);
    uint32_t* hp = reinterpret_cast<uint32_t*>(hi);
    uint32_t* lp = reinterpret_cast<uint32_t*>(lo);
    hp[2*i] = h0; hp[2*i+1] = h1;
    lp[2*i] = l0; lp[2*i+1] = l1;
}

__global__ __launch_bounds__(256)
void split_w(const float* __restrict__ w0, const float* __restrict__ w1,
             const float* __restrict__ w2, const float* __restrict__ w3)
{
    int z = blockIdx.z;
    const float* src = (z == 0) ? w0 : (z == 1) ? w1 : (z == 2) ? w2 : w3;
    __nv_bfloat16* hi = (z == 0) ? g_wq_h : (z == 1) ? g_wk_h
                      : (z == 2) ? g_wv_h : g_wo_h;
    __nv_bfloat16* lo = (z == 0) ? g_wq_l : (z == 1) ? g_wk_l
                      : (z == 2) ? g_wv_l : g_wo_l;
    int i = blockIdx.x * blockDim.x + threadIdx.x;
    float4 f = reinterpret_cast<const float4*>(src)[i];
    uint32_t h0, l0, h1, l1;
    split2(f.x, f.y, h0, l0);
    split2(f.z, f.w, h1, l1);
    uint32_t* hp = reinterpret_cast<uint32_t*>(hi);
    uint32_t* lp = reinterpret_cast<uint32_t*>(lo);
    hp[2*i] = h0; hp[2*i+1] = h1;
    lp[2*i] = l0; lp[2*i+1] = l1;
}

// ---------------------------------------------------------------------------
// GEMM mainloop core (shared by qkv_gemm / out_gemm).
// Block 128x128, BK=32, 8 warps, 3-term hi/lo HMMA. Register-lean ordering.
// ---------------------------------------------------------------------------
#define ROW_B   80
#define TILE_B  (128 * ROW_B)
#define STAGE_B (4 * TILE_B)             // 40960 B
#define NCHUNK  (DD / 32)                // 24

__device__ __forceinline__ void gemm_core(
    const __nv_bfloat16* __restrict__ Ah, const __nv_bfloat16* __restrict__ Al,
    const __nv_bfloat16* __restrict__ Bh, const __nv_bfloat16* __restrict__ Bl,
    uint32_t sbase, int tid, float acc[2][8][4])
{
    const int wid = tid >> 5, lane = tid & 31;
    const int wm = wid & 3, wn = wid >> 2;

    const __nv_bfloat16* srcs[4] = {Ah, Al, Bh, Bl};

    auto load_chunk = [&](int kc, int st) {
        const int k0 = kc * 32;
        #pragma unroll
        for (int t = 0; t < 8; t++) {
            int id   = tid + t * 256;
            int tile = id >> 9;
            int rem  = id & 511;
            int row  = rem >> 2;
            int seg  = rem & 3;
            const __nv_bfloat16* g = srcs[tile] + (size_t)row * DD + k0 + seg * 8;
            uint32_t s = sbase + st * STAGE_B + tile * TILE_B + row * ROW_B + seg * 16;
            cp_async16(s, g);
        }
        cp_commit();
    };

    load_chunk(0, 0);

    const int lrow = lane & 15;
    const int lhalf = lane >> 4;

    #pragma unroll 1
    for (int c = 0; c < NCHUNK; c++) {
        const int s = c & 1;
        if (c + 1 < NCHUNK) { load_chunk(c + 1, s ^ 1); cp_wait<1>(); }
        else                { cp_wait<0>(); }
        __syncthreads();

        const uint32_t stg = sbase + s * STAGE_B;

        #pragma unroll
        for (int ks = 0; ks < 2; ks++) {
            const int seg = ks * 2 + lhalf;
            uint32_t ah[2][4], al[2][4];
            #pragma unroll
            for (int mf = 0; mf < 2; mf++) {
                uint32_t off = (uint32_t)((wm * 32 + mf * 16 + lrow) * ROW_B + seg * 16);
                ldmatrix_x4(ah[mf][0], ah[mf][1], ah[mf][2], ah[mf][3], stg + off);
                ldmatrix_x4(al[mf][0], al[mf][1], al[mf][2], al[mf][3], stg + TILE_B + off);
            }
            #pragma unroll
            for (int ng = 0; ng < 4; ng++) {
                uint32_t off = (uint32_t)((wn * 64 + ng * 16 + lrow) * ROW_B + seg * 16);
                uint32_t b0, b1, b2, b3, c0, c1, c2, c3;
                ldmatrix_x4(b0, b1, b2, b3, stg + 2*TILE_B + off);
                ldmatrix_x4(c0, c1, c2, c3, stg + 3*TILE_B + off);
                #pragma unroll
                for (int mf = 0; mf < 2; mf++) {
                    mma_bf16(acc[mf][2*ng  ], ah[mf], b0, b2);
                    mma_bf16(acc[mf][2*ng+1], ah[mf], b1, b3);
                    mma_bf16(acc[mf][2*ng  ], ah[mf], c0, c2);
                    mma_bf16(acc[mf][2*ng+1], ah[mf], c1, c3);
                    mma_bf16(acc[mf][2*ng  ], al[mf], b0, b2);
                    mma_bf16(acc[mf][2*ng+1], al[mf], b1, b3);
                }
            }
        }
        __syncthreads();
    }
}

// Fused Q/K/V projection GEMMs (z selects operand set). Epilogue: scale,
// bf16 hi/lo split, scatter to [B,H,L,Dh]. Q pre-scaled by log2e/sqrt(Dh).
__global__ __launch_bounds__(256, 2)
void qkv_gemm(const float* __restrict__ bq, const float* __restrict__ bk,
              const float* __restrict__ bv)
{
    extern __shared__ __align__(128) char smem[];
    const int z = blockIdx.z;
    const int m0 = blockIdx.y * 128, n0 = blockIdx.x * 128;
    const int tid = threadIdx.x;
    const int wid = tid >> 5, lane = tid & 31;
    const int wm = wid & 3, wn = wid >> 2;

    const __nv_bfloat16* Ah = (z == 0) ? g_xq_h : (z == 1) ? g_xk_h : g_xv_h;
    const __nv_bfloat16* Al = (z == 0) ? g_xq_l : (z == 1) ? g_xk_l : g_xv_l;
    const __nv_bfloat16* Bh = (z == 0) ? g_wq_h : (z == 1) ? g_wk_h : g_wv_h;
    const __nv_bfloat16* Bl = (z == 0) ? g_wq_l : (z == 1) ? g_wk_l : g_wv_l;
    const float* bias = (z == 0) ? bq : (z == 1) ? bk : bv;
    __nv_bfloat16* oh = (z == 0) ? g_qh : (z == 1) ? g_kh : g_vh;
    __nv_bfloat16* ol = (z == 0) ? g_ql : (z == 1) ? g_kl : g_vl;
    const float scale = (z == 0) ? 0.125f * LOG2E : 1.0f;

    float acc[2][8][4];
    #pragma unroll
    for (int i = 0; i < 2; i++)
        #pragma unroll
        for (int j = 0; j < 8; j++)
            #pragma unroll
            for (int k = 0; k < 4; k++) acc[i][j][k] = 0.f;

    gemm_core(Ah + (size_t)m0 * DD, Al + (size_t)m0 * DD,
              Bh + (size_t)n0 * DD, Bl + (size_t)n0 * DD,
              smem_u32(smem), tid, acc);

    #pragma unroll
    for (int nf = 0; nf < 8; nf++) {
        const int col = n0 + wn * 64 + nf * 8 + (lane & 3) * 2;
        const float b0 = bias[col], b1 = bias[col + 1];
        #pragma unroll
        for (int mf = 0; mf < 2; mf++) {
            const int r0 = m0 + wm * 32 + mf * 16 + (lane >> 2);
            const float* a = acc[mf][nf];
            #pragma unroll
            for (int half = 0; half < 2; half++) {
                const int m = r0 + half * 8;
                float v0 = (a[2*half] + b0) * scale, v1 = (a[2*half+1] + b1) * scale;
                uint32_t hp, lp;
                split2(v0, v1, hp, lp);
                int bb = m >> 10, l = m & 1023;
                int hh = col >> 6, d = col & 63;
                size_t idx = (((size_t)(bb * HH + hh) << 10) + l) * DHH + d;
                *reinterpret_cast<uint32_t*>(oh + idx) = hp;
                *reinterpret_cast<uint32_t*>(ol + idx) = lp;
            }
        }
    }
}

// Output projection GEMM: fp32 d_out.
__global__ __launch_bounds__(256, 2)
void out_gemm(const float* __restrict__ bias, float* __restrict__ out)
{
    extern __shared__ __align__(128) char smem[];
    const int m0 = blockIdx.y * 128, n0 = blockIdx.x * 128;
    const int tid = threadIdx.x;
    const int wid = tid >> 5, lane = tid & 31;
    const int wm = wid & 3, wn = wid >> 2;

    float acc[2][8][4];
    #pragma unroll
    for (int i = 0; i < 2; i++)
        #pragma unroll
        for (int j = 0; j < 8; j++)
            #pragma unroll
            for (int k = 0; k < 4; k++) acc[i][j][k] = 0.f;

    gemm_core(g_ch + (size_t)m0 * DD, g_cl + (size_t)m0 * DD,
              g_wo_h + (size_t)n0 * DD, g_wo_l + (size_t)n0 * DD,
              smem_u32(smem), tid, acc);

    #pragma unroll
    for (int nf = 0; nf < 8; nf++) {
        const int col = n0 + wn * 64 + nf * 8 + (lane & 3) * 2;
        const float b0 = bias[col], b1 = bias[col + 1];
        #pragma unroll
        for (int mf = 0; mf < 2; mf++) {
            const int r0 = m0 + wm * 32 + mf * 16 + (lane >> 2);
            const float* a = acc[mf][nf];
            #pragma unroll
            for (int half = 0; half < 2; half++) {
                const int m = r0 + half * 8;
                *reinterpret_cast<float2*>(out + (size_t)m * DD + col)
                    = make_float2(a[2*half] + b0, a[2*half+1] + b1);
            }
        }
    }
}

// ---------------------------------------------------------------------------
// HMMA flash attention (log2-domain softmax; exp2f).
// ---------------------------------------------------------------------------
#define AROWB   144
#define ATILE_B (128 * AROWB)           // 18432 B
#define KVSTG_B (4 * ATILE_B)           // 73728 B
#define ASMEM   (2 * ATILE_B + 2 * KVSTG_B)   // 184320 B

__global__ __launch_bounds__(256, 1)
void attn_mma()
{
    extern __shared__ __align__(128) char smem[];
    const uint32_t sb = smem_u32(smem);
    const int tid = threadIdx.x, wid = tid >> 5, lane = tid & 31;
    const int qt = blockIdx.x, h = blockIdx.y, b = blockIdx.z;
    const int q0 = qt * 128;
    const size_t hb = ((size_t)(b * HH + h)) << 16;

    const uint32_t SQH = sb, SQL = sb + ATILE_B;
    auto stage = [&](int s) { return sb + 2 * ATILE_B + (uint32_t)s * KVSTG_B; };

    auto load_tile = [&](const __nv_bfloat16* g, uint32_t s) {
        #pragma unroll
        for (int it = 0; it < 4; it++) {
            int id = tid + it * 256;
            int row = id >> 3, seg = id & 7;
            cp_async16(s + row * AROWB + seg * 16, g + (size_t)row * 64 + seg * 8);
        }
    };
    auto load_kv = [&](int t, int s) {
        const size_t off = hb + (size_t)t * 128 * 64;
        uint32_t st = stage(s);
        load_tile(g_kh + off, st);
        load_tile(g_kl + off, st + ATILE_B);
        load_tile(g_vh + off, st + 2 * ATILE_B);
        load_tile(g_vl + off, st + 3 * ATILE_B);
        cp_commit();
    };

    load_tile(g_qh + hb + (size_t)q0 * 64, SQH);
    load_tile(g_ql + hb + (size_t)q0 * 64, SQL);
    cp_commit();
    load_kv(0, 0);
    cp_wait<1>();
    __syncthreads();

    const int lr = lane & 15, lh = lane >> 4;
    uint32_t qfh[4][4], qfl[4][4];
    #pragma unroll
    for (int ks = 0; ks < 4; ks++) {
        uint32_t off = (uint32_t)((wid * 16 + lr) * AROWB + ks * 32 + lh * 16);
        ldmatrix_x4(qfh[ks][0], qfh[ks][1], qfh[ks][2], qfh[ks][3], SQH + off);
        ldmatrix_x4(qfl[ks][0], qfl[ks][1], qfl[ks][2], qfl[ks][3], SQL + off);
    }

    float mA = -INFINITY, mB = -INFINITY, lA = 0.f, lB = 0.f;
    float o[8][4];
    #pragma unroll
    for (int i = 0; i < 8; i++)
        #pragma unroll
        for (int j = 0; j < 4; j++) o[i][j] = 0.f;

    const unsigned char* flagp = g_mflags + (b * 8 + qt) * 8;

    #pragma unroll 1
    for (int t = 0; t < 8; t++) {
        if (t < 7) { load_kv(t + 1, (t + 1) & 1); cp_wait<1>(); }
        else       { cp_wait<0>(); }
        __syncthreads();
        const uint32_t st = stage(t & 1);

        // ---- S = Q @ K^T (3 terms) ----
        float s[16][4];
        #pragma unroll
        for (int j = 0; j < 16; j++)
            #pragma unroll
            for (int k = 0; k < 4; k++) s[j][k] = 0.f;

        #pragma unroll
        for (int ks = 0; ks < 4; ks++) {
            #pragma unroll
            for (int ng = 0; ng < 8; ng++) {
                uint32_t off = (uint32_t)((ng * 16 + lr) * AROWB + ks * 32 + lh * 16);
                uint32_t k0, k1, k2, k3, l0, l1, l2, l3;
                ldmatrix_x4(k0, k1, k2, k3, st + off);
                ldmatrix_x4(l0, l1, l2, l3, st + ATILE_B + off);
                mma_bf16(s[2*ng  ], qfh[ks], k0, k2);
                mma_bf16(s[2*ng+1], qfh[ks], k1, k3);
                mma_bf16(s[2*ng  ], qfh[ks], l0, l2);
                mma_bf16(s[2*ng+1], qfh[ks], l1, l3);
                mma_bf16(s[2*ng  ], qfl[ks], k0, k2);
                mma_bf16(s[2*ng+1], qfl[ks], k1, k3);
            }
        }

        // ---- mask (rare path) ----
        if (flagp[t]) {
            const uint32_t* mr = g_mbits
                + ((size_t)(b * LL + q0 + wid * 16 + (lane >> 2))) * (LL / 32) + t * 4;
            uint32_t wA[4], wB[4];
            #pragma unroll
            for (int ww = 0; ww < 4; ww++) { wA[ww] = mr[ww]; wB[ww] = mr[8 * (LL/32) + ww]; }
            #pragma unroll
            for (int j = 0; j < 16; j++) {
                int bp = (j & 3) * 8 + (lane & 3) * 2;
                uint32_t a = wA[j >> 2], bw = wB[j >> 2];
                if ((a  >> bp)      & 1u) s[j][0] = -INFINITY;
                if ((a  >> (bp+1))  & 1u) s[j][1] = -INFINITY;
                if ((bw >> bp)      & 1u) s[j][2] = -INFINITY;
                if ((bw >> (bp+1))  & 1u) s[j][3] = -INFINITY;
            }
        }

        // ---- online softmax in log2 domain ----
        float mxA = -INFINITY, mxB = -INFINITY;
        #pragma unroll
        for (int j = 0; j < 16; j++) {
            mxA = fmaxf(mxA, fmaxf(s[j][0], s[j][1]));
            mxB = fmaxf(mxB, fmaxf(s[j][2], s[j][3]));
        }
        mxA = fmaxf(mxA, __shfl_xor_sync(0xffffffffu, mxA, 1));
        mxA = fmaxf(mxA, __shfl_xor_sync(0xffffffffu, mxA, 2));
        mxB = fmaxf(mxB, __shfl_xor_sync(0xffffffffu, mxB, 1));
        mxB = fmaxf(mxB, __shfl_xor_sync(0xffffffffu, mxB, 2));
        float mnA = fmaxf(mA, mxA), mnB = fmaxf(mB, mxB);
        float aA = (mA == -INFINITY) ? 0.f : exp2f(mA - mnA);
        float aB = (mB == -INFINITY) ? 0.f : exp2f(mB - mnB);
        float subA = (mnA == -INFINITY) ? 0.f : mnA;
        float subB = (mnB == -INFINITY) ? 0.f : mnB;
        float sA = 0.f, sB = 0.f;
        #pragma unroll
        for (int j = 0; j < 16; j++) {
            s[j][0] = exp2f(s[j][0] - subA);
            s[j][1] = exp2f(s[j][1] - subA);
            s[j][2] = exp2f(s[j][2] - subB);
            s[j][3] = exp2f(s[j][3] - subB);
            sA += s[j][0] + s[j][1];
            sB += s[j][2] + s[j][3];
        }
        sA += __shfl_xor_sync(0xffffffffu, sA, 1);
        sA += __shfl_xor_sync(0xffffffffu, sA, 2);
        sB += __shfl_xor_sync(0xffffffffu, sB, 1);
        sB += __shfl_xor_sync(0xffffffffu, sB, 2);
        lA = lA * aA + sA; lB = lB * aB + sB;
        mA = mnA; mB = mnB;
        #pragma unroll
        for (int nf = 0; nf < 8; nf++) {
            o[nf][0] *= aA; o[nf][1] *= aA;
            o[nf][2] *= aB; o[nf][3] *= aB;
        }

        // ---- O += P @ V (3 terms) ----
        #pragma unroll
        for (int ks = 0; ks < 8; ks++) {
            uint32_t aph[4], apl[4];
            split2(s[2*ks  ][0], s[2*ks  ][1], aph[0], apl[0]);
            split2(s[2*ks  ][2], s[2*ks  ][3], aph[1], apl[1]);
            split2(s[2*ks+1][0], s[2*ks+1][1], aph[2], apl[2]);
            split2(s[2*ks+1][2], s[2*ks+1][3], aph[3], apl[3]);
            #pragma unroll
            for (int ng = 0; ng < 4; ng++) {
                uint32_t voff = (uint32_t)((ks * 16 + lr) * AROWB + ng * 32 + lh * 16);
                uint32_t v0, v1, v2, v3, w0, w1, w2, w3;
                ldmatrix_x4_t(v0, v1, v2, v3, st + 2 * ATILE_B + voff);
                ldmatrix_x4_t(w0, w1, w2, w3, st + 3 * ATILE_B + voff);
                mma_bf16(o[2*ng  ], aph, v0, v1);
                mma_bf16(o[2*ng+1], aph, v2, v3);
                mma_bf16(o[2*ng  ], aph, w0, w1);
                mma_bf16(o[2*ng+1], aph, w2, w3);
                mma_bf16(o[2*ng  ], apl, v0, v1);
                mma_bf16(o[2*ng+1], apl, v2, v3);
            }
        }
        __syncthreads();
    }

    // ---- epilogue ----
    float iA = (lA > 0.f) ? (1.f / lA) : 0.f;
    float iB = (lB > 0.f) ? (1.f / lB) : 0.f;
    size_t rowA = (size_t)b * LL + q0 + wid * 16 + (lane >> 2);
    size_t rowB = rowA + 8;
    #pragma unroll
    for (int nf = 0; nf < 8; nf++) {
        int col = h * 64 + nf * 8 + (lane & 3) * 2;
        uint32_t hp, lp;
        split2(o[nf][0] * iA, o[nf][1] * iA, hp, lp);
        *reinterpret_cast<uint32_t*>(g_ch + rowA * DD + col) = hp;
        *reinterpret_cast<uint32_t*>(g_cl + rowA * DD + col) = lp;
        split2(o[nf][2] * iB, o[nf][3] * iB, hp, lp);
        *reinterpret_cast<uint32_t*>(g_ch + rowB * DD + col) = hp;
        *reinterpret_cast<uint32_t*>(g_cl + rowB * DD + col) = lp;
    }
}

// ---------------------------------------------------------------------------
extern "C" void kernel_launch(void* const* d_in, const int* in_sizes, int n_in,
                              void* d_out, int out_size)
{
    const float* Query = (const float*)d_in[0];
    const float* Key   = (const float*)d_in[1];
    const float* Value = (const float*)d_in[2];
    const unsigned char* maskp = (const unsigned char*)d_in[3];
    const float* WQ_b = (const float*)d_in[5];
    const float* WK_b = (const float*)d_in[7];
    const float* WV_b = (const float*)d_in[9];
    const float* WO_b = (const float*)d_in[11];
    float* out = (float*)d_out;

    cudaFuncSetAttribute(qkv_gemm, cudaFuncAttributeMaxDynamicSharedMemorySize,
                         2 * STAGE_B);
    cudaFuncSetAttribute(out_gemm, cudaFuncAttributeMaxDynamicSharedMemorySize,
                         2 * STAGE_B);
    cudaFuncSetAttribute(attn_mma, cudaFuncAttributeMaxDynamicSharedMemorySize,
                         ASMEM);

    // Mask preprocessing
    pack_mask<<<BB * LL * (LL / 32) / 256, 256>>>(maskp);
    mask_flags<<<dim3(8, 8, 8), 128>>>();

    // Splits (fused launches)
    split_w<<<dim3(DD * DD / 4 / 256, 1, 4), 256>>>(
        (const float*)d_in[4], (const float*)d_in[6],
        (const float*)d_in[8], (const float*)d_in[10]);
    split_x<<<dim3(MM * DD / 4 / 256, 1, 3), 256>>>(Query, Key, Value);

    // Fused Q/K/V projections
    qkv_gemm<<<dim3(DD / 128, MM / 128, 3), 256, 2 * STAGE_B>>>(WQ_b, WK_b, WV_b);

    // Attention
    attn_mma<<<dim3(LL / 128, HH, BB), 256, ASMEM>>>();

    // Output projection
    out_gemm<<<dim3(DD / 128, MM / 128), 256, 2 * STAGE_B>>>(WO_b, out);
}